// round 15
// baseline (speedup 1.0000x reference)
#include <cuda_runtime.h>
#include <cuda_bf16.h>
#include <cuda_fp16.h>
#include <cstdint>
#include <math.h>

// GIN layer: out = h + relu(BN(relu(((1+eps)h + segsum(h[src]->dst)) @ W1 + b1) @ W2 + b2))
// Bucket CSR + fused gather->GEMM1->GEMM2 (split-bf16 mma.sync).
// Gather: fp16 rows, register-resident indices (shfl), double-buffered batches.
#define D 128
#define MAXN 100000
#define CAP 96

// ---- scratch (__device__ globals; alloc-free rule) ----
__device__ float4 g_buf1_v4[MAXN * (D / 4)];   // y2
__device__ uint2 g_hhalf[MAXN * (D / 4)];      // h in fp16 (32 uint2 per row)
__device__ int g_cnt[MAXN];                    // per-node degree counters
__device__ int g_bucket[MAXN * CAP];           // src lists grouped by dst
__device__ uint4 g_wf1[4096], g_wf2[4096];     // W fragments (mma B layout, hi/lo interleaved)
__device__ float g_sum[D], g_sumsq[D];

// ---------------------------------------------------------------------------
__device__ __forceinline__ void split2(float2 v, uint32_t& hi, uint32_t& lo) {
    __nv_bfloat162 h = __floats2bfloat162_rn(v.x, v.y);
    float2 hf = __bfloat1622float2(h);
    __nv_bfloat162 l = __floats2bfloat162_rn(v.x - hf.x, v.y - hf.y);
    hi = *(uint32_t*)&h;
    lo = *(uint32_t*)&l;
}

__device__ __forceinline__ void mma16816(float* c, const uint32_t* a,
                                         uint32_t b0, uint32_t b1) {
    asm volatile(
        "mma.sync.aligned.m16n8k16.row.col.f32.bf16.bf16.f32 "
        "{%0,%1,%2,%3}, {%4,%5,%6,%7}, {%8,%9}, {%0,%1,%2,%3};"
        : "+f"(c[0]), "+f"(c[1]), "+f"(c[2]), "+f"(c[3])
        : "r"(a[0]), "r"(a[1]), "r"(a[2]), "r"(a[3]), "r"(b0), "r"(b1));
}

__device__ __forceinline__ void acc_half4(float4& acc, uint2 q) {
    __half2 a01 = *(__half2*)&q.x;
    __half2 a23 = *(__half2*)&q.y;
    float2 f01 = __half22float2(a01);
    float2 f23 = __half22float2(a23);
    acc.x += f01.x; acc.y += f01.y; acc.z += f23.x; acc.w += f23.y;
}

// ---------------------------------------------------------------------------
// K1: zero counters + stats; 2 blocks do W fragment prep; HB blocks convert h->fp16.
// ---------------------------------------------------------------------------
__global__ __launch_bounds__(256) void k_zero_wprep(const float* __restrict__ h,
                                                    const float* __restrict__ W1,
                                                    const float* __restrict__ W2,
                                                    int N, int NB, int nvec) {
    int b = blockIdx.x;
    if (b < NB) {
        int i = b * 256 + threadIdx.x;
        if (i < N) g_cnt[i] = 0;
        if (b == 0 && threadIdx.x < D) {
            g_sum[threadIdx.x] = 0.f;
            g_sumsq[threadIdx.x] = 0.f;
        }
        return;
    }
    if (b < NB + 2) {
        const float* W = (b == NB) ? W1 : W2;
        uint4* wf = (b == NB) ? g_wf1 : g_wf2;
        for (int item = threadIdx.x; item < 4096; item += 256) {
            int ks = item >> 9;
            int nt = (item >> 5) & 15;
            int lane = item & 31;
            int n = nt * 8 + (lane >> 2);
            int k0 = ks * 16 + (lane & 3) * 2;
            float2 p0 = make_float2(W[k0 * D + n], W[(k0 + 1) * D + n]);
            float2 p1 = make_float2(W[(k0 + 8) * D + n], W[(k0 + 9) * D + n]);
            uint4 q;
            split2(p0, q.x, q.z);
            split2(p1, q.y, q.w);
            wf[item] = q;
        }
        return;
    }
    int idx = (b - NB - 2) * 256 + threadIdx.x;
    if (idx < nvec) {
        float4 v = ((const float4*)h)[idx];
        __half2 h01 = __floats2half2_rn(v.x, v.y);
        __half2 h23 = __floats2half2_rn(v.z, v.w);
        g_hhalf[idx] = make_uint2(*(uint32_t*)&h01, *(uint32_t*)&h23);
    }
}

// ---------------------------------------------------------------------------
// K2: one-pass bucketed edge placement.
// ---------------------------------------------------------------------------
__global__ __launch_bounds__(256) void k_place(const int* __restrict__ src,
                                               const int* __restrict__ dst, int E) {
    int e = blockIdx.x * 256 + threadIdx.x;
    if (e >= E) return;
    int d = dst[e];
    int pos = atomicAdd(&g_cnt[d], 1);
    if (pos < CAP) g_bucket[(size_t)d * CAP + pos] = src[e];
}

// ---------------------------------------------------------------------------
// Fused: gather-aggregate + MLP. CTA = 64 nodes, 8 warps, warp w -> nodes w*8..+7.
// Phase A: gather. Indices preloaded into 3 regs/lane (coalesced) and shfl'd out;
//          fp16 neighbor rows in double-buffered 8-row batches (uint2 staging).
// Phase B: stage-1 GEMM, relu(+b1) overwrites planes.
// Phase C: stage-2 GEMM -> y2 gmem + fused BN column stats.
// Pitch 136 elems (68 words/row, mod 32 = 4) -> conflict-free fragment LDS.
// ---------------------------------------------------------------------------
#define PITCH 136
#define TILE 64
__global__ __launch_bounds__(256, 2) void k_fused(
    const float* __restrict__ h, const float* __restrict__ eps,
    const uint4* __restrict__ W1f, const uint4* __restrict__ W2f,
    const float* __restrict__ b1, const float* __restrict__ b2,
    float* __restrict__ Y, int N) {
    __shared__ __nv_bfloat16 plhi[TILE * PITCH];
    __shared__ __nv_bfloat16 pllo[TILE * PITCH];
    __shared__ float csum[D], csumsq[D];

    const int t = threadIdx.x;
    const int w = t >> 5;
    const int lane = t & 31;

    if (t < D) { csum[t] = 0.f; csumsq[t] = 0.f; }

    // ---------------- Phase A: gather ----------------
    {
        const float4* h4 = (const float4*)h;
        const float s = 1.0f + eps[0];
        #pragma unroll 1
        for (int i = 0; i < 8; i++) {
            int nl = w * 8 + i;
            int n = blockIdx.x * TILE + nl;
            float4 acc = make_float4(0.f, 0.f, 0.f, 0.f);
            if (n < N) {
                acc = __ldg(&h4[(size_t)n * 32 + lane]);
                acc.x *= s; acc.y *= s; acc.z *= s; acc.w *= s;
                int deg = min(g_cnt[n], CAP);
                const int* bucket = g_bucket + (size_t)n * CAP;
                // indices -> registers (coalesced, predicated), shfl on use
                int i0 = (lane < deg) ? __ldg(&bucket[lane]) : 0;
                int i1 = (lane + 32 < deg) ? __ldg(&bucket[lane + 32]) : 0;
                int i2 = (lane + 64 < deg) ? __ldg(&bucket[lane + 64]) : 0;

                const uint2 Z = make_uint2(0u, 0u);  // fp16 zeros
                // first batch
                uint2 bufA[8];
                #pragma unroll
                for (int u = 0; u < 8; u++) {
                    int idx = __shfl_sync(0xFFFFFFFF, i0, u);
                    bufA[u] = (u < deg) ? __ldg(&g_hhalf[(size_t)idx * 32 + lane]) : Z;
                }
                #pragma unroll 1
                for (int j = 8; j < deg; j += 8) {
                    uint2 bufB[8];
                    #pragma unroll
                    for (int u = 0; u < 8; u++) {
                        int jj = j + u;
                        int v = (jj < 32) ? i0 : (jj < 64) ? i1 : i2;
                        int idx = __shfl_sync(0xFFFFFFFF, v, jj & 31);
                        bufB[u] = (jj < deg) ? __ldg(&g_hhalf[(size_t)idx * 32 + lane]) : Z;
                    }
                    // accumulate previous batch while bufB loads are in flight
                    #pragma unroll
                    for (int u = 0; u < 8; u++) acc_half4(acc, bufA[u]);
                    #pragma unroll
                    for (int u = 0; u < 8; u++) bufA[u] = bufB[u];
                }
                #pragma unroll
                for (int u = 0; u < 8; u++) acc_half4(acc, bufA[u]);
            }
            uint32_t hi01, lo01, hi23, lo23;
            split2(make_float2(acc.x, acc.y), hi01, lo01);
            split2(make_float2(acc.z, acc.w), hi23, lo23);
            *(uint2*)&plhi[nl * PITCH + lane * 4] = make_uint2(hi01, hi23);
            *(uint2*)&pllo[nl * PITCH + lane * 4] = make_uint2(lo01, lo23);
        }
    }
    __syncthreads();

    const int rloc = (w >> 1) * 16 + (lane >> 2);
    const int r0 = blockIdx.x * TILE + rloc;
    const int kq = (lane & 3) * 2;
    const int nhalf = w & 1;
    const bool rv0 = r0 < N;
    const bool rv1 = (r0 + 8) < N;

    float acc[8][4];

    // ---------------- Phase B: stage-1 GEMM ----------------
    #pragma unroll
    for (int nt = 0; nt < 8; nt++)
        #pragma unroll
        for (int j = 0; j < 4; j++) acc[nt][j] = 0.f;

    #pragma unroll
    for (int ks = 0; ks < 8; ks++) {
        const int k0 = ks * 16 + kq;
        uint32_t ah[4], al[4];
        ah[0] = *(const uint32_t*)&plhi[rloc * PITCH + k0];
        ah[1] = *(const uint32_t*)&plhi[(rloc + 8) * PITCH + k0];
        ah[2] = *(const uint32_t*)&plhi[rloc * PITCH + k0 + 8];
        ah[3] = *(const uint32_t*)&plhi[(rloc + 8) * PITCH + k0 + 8];
        al[0] = *(const uint32_t*)&pllo[rloc * PITCH + k0];
        al[1] = *(const uint32_t*)&pllo[(rloc + 8) * PITCH + k0];
        al[2] = *(const uint32_t*)&pllo[rloc * PITCH + k0 + 8];
        al[3] = *(const uint32_t*)&pllo[(rloc + 8) * PITCH + k0 + 8];
        #pragma unroll
        for (int nt = 0; nt < 8; nt++) {
            uint4 q = __ldg(&W1f[(ks * 16 + nhalf * 8 + nt) * 32 + lane]);
            mma16816(acc[nt], ah, q.x, q.y);
            mma16816(acc[nt], al, q.x, q.y);
            mma16816(acc[nt], ah, q.z, q.w);
        }
    }
    __syncthreads();   // all reads of x planes done before overwrite

    // stage-1 epilogue: relu(acc+b1) -> planes (reuse)
    #pragma unroll
    for (int nt = 0; nt < 8; nt++) {
        const int n0 = nhalf * 64 + nt * 8 + kq;
        float2 bv = __ldg((const float2*)(b1 + n0));
        float2 p0 = make_float2(fmaxf(acc[nt][0] + bv.x, 0.f),
                                fmaxf(acc[nt][1] + bv.y, 0.f));
        float2 p1 = make_float2(fmaxf(acc[nt][2] + bv.x, 0.f),
                                fmaxf(acc[nt][3] + bv.y, 0.f));
        uint32_t hi0, lo0, hi1, lo1;
        split2(p0, hi0, lo0);
        split2(p1, hi1, lo1);
        *(uint32_t*)&plhi[rloc * PITCH + n0] = hi0;
        *(uint32_t*)&pllo[rloc * PITCH + n0] = lo0;
        *(uint32_t*)&plhi[(rloc + 8) * PITCH + n0] = hi1;
        *(uint32_t*)&pllo[(rloc + 8) * PITCH + n0] = lo1;
    }
    __syncthreads();

    // ---------------- Phase C: stage-2 GEMM ----------------
    #pragma unroll
    for (int nt = 0; nt < 8; nt++)
        #pragma unroll
        for (int j = 0; j < 4; j++) acc[nt][j] = 0.f;

    #pragma unroll
    for (int ks = 0; ks < 8; ks++) {
        const int k0 = ks * 16 + kq;
        uint32_t ah[4], al[4];
        ah[0] = *(const uint32_t*)&plhi[rloc * PITCH + k0];
        ah[1] = *(const uint32_t*)&plhi[(rloc + 8) * PITCH + k0];
        ah[2] = *(const uint32_t*)&plhi[rloc * PITCH + k0 + 8];
        ah[3] = *(const uint32_t*)&plhi[(rloc + 8) * PITCH + k0 + 8];
        al[0] = *(const uint32_t*)&pllo[rloc * PITCH + k0];
        al[1] = *(const uint32_t*)&pllo[(rloc + 8) * PITCH + k0];
        al[2] = *(const uint32_t*)&pllo[rloc * PITCH + k0 + 8];
        al[3] = *(const uint32_t*)&pllo[(rloc + 8) * PITCH + k0 + 8];
        #pragma unroll
        for (int nt = 0; nt < 8; nt++) {
            uint4 q = __ldg(&W2f[(ks * 16 + nhalf * 8 + nt) * 32 + lane]);
            mma16816(acc[nt], ah, q.x, q.y);
            mma16816(acc[nt], al, q.x, q.y);
            mma16816(acc[nt], ah, q.z, q.w);
        }
    }

    // stage-2 epilogue: + b2, write y2, fused BN stats
    #pragma unroll
    for (int nt = 0; nt < 8; nt++) {
        const int n0 = nhalf * 64 + nt * 8 + kq;
        float2 bv = __ldg((const float2*)(b2 + n0));
        float ox0 = acc[nt][0] + bv.x;
        float oy0 = acc[nt][1] + bv.y;
        float ox1 = acc[nt][2] + bv.x;
        float oy1 = acc[nt][3] + bv.y;
        float sA = 0.f, sB = 0.f, qA = 0.f, qB = 0.f;
        if (rv0) {
            *(float2*)(Y + (size_t)r0 * D + n0) = make_float2(ox0, oy0);
            sA += ox0; qA = fmaf(ox0, ox0, qA);
            sB += oy0; qB = fmaf(oy0, oy0, qB);
        }
        if (rv1) {
            *(float2*)(Y + (size_t)(r0 + 8) * D + n0) = make_float2(ox1, oy1);
            sA += ox1; qA = fmaf(ox1, ox1, qA);
            sB += oy1; qB = fmaf(oy1, oy1, qB);
        }
        #pragma unroll
        for (int off = 4; off <= 16; off <<= 1) {
            sA += __shfl_xor_sync(0xFFFFFFFF, sA, off);
            sB += __shfl_xor_sync(0xFFFFFFFF, sB, off);
            qA += __shfl_xor_sync(0xFFFFFFFF, qA, off);
            qB += __shfl_xor_sync(0xFFFFFFFF, qB, off);
        }
        if (lane < 4) {
            atomicAdd(&csum[n0], sA);
            atomicAdd(&csum[n0 + 1], sB);
            atomicAdd(&csumsq[n0], qA);
            atomicAdd(&csumsq[n0 + 1], qB);
        }
    }

    __syncthreads();
    if (t < D) {
        atomicAdd(&g_sum[t], csum[t]);
        atomicAdd(&g_sumsq[t], csumsq[t]);
    }
}

// ---------------------------------------------------------------------------
// Epilogue (merged BN finalize): out = h + relu(y2 * scale + shift)
// ---------------------------------------------------------------------------
__global__ __launch_bounds__(256) void k_epilogue(const float* __restrict__ h,
                                                  const float* __restrict__ gamma,
                                                  const float* __restrict__ beta,
                                                  float* __restrict__ out,
                                                  float invN, int n_elem4) {
    __shared__ float s_scale[D], s_shift[D];
    if (threadIdx.x < D) {
        int c = threadIdx.x;
        float mean = g_sum[c] * invN;
        float var = g_sumsq[c] * invN - mean * mean;
        float rstd = rsqrtf(var + 1e-5f);
        float sc = rstd * gamma[c];
        s_scale[c] = sc;
        s_shift[c] = beta[c] - mean * sc;
    }
    __syncthreads();
    int i = blockIdx.x * blockDim.x + threadIdx.x;
    int stride = gridDim.x * blockDim.x;
    const float4* h4 = (const float4*)h;
    float4* o4 = (float4*)out;
    for (; i < n_elem4; i += stride) {
        int c4 = (i & 31);
        float4 sc = ((const float4*)s_scale)[c4];
        float4 sh = ((const float4*)s_shift)[c4];
        float4 y = g_buf1_v4[i];
        float4 hv = h4[i];
        float4 o;
        o.x = hv.x + fmaxf(fmaf(y.x, sc.x, sh.x), 0.f);
        o.y = hv.y + fmaxf(fmaf(y.y, sc.y, sh.y), 0.f);
        o.z = hv.z + fmaxf(fmaf(y.z, sc.z, sh.z), 0.f);
        o.w = hv.w + fmaxf(fmaf(y.w, sc.w, sh.w), 0.f);
        o4[i] = o;
    }
}

// ---------------------------------------------------------------------------
// Inputs: h, src, dst, eps, W1, b1, W2, b2, gamma, beta
// ---------------------------------------------------------------------------
extern "C" void kernel_launch(void* const* d_in, const int* in_sizes, int n_in,
                              void* d_out, int out_size) {
    const float* h     = (const float*)d_in[0];
    const int*   src   = (const int*)d_in[1];
    const int*   dst   = (const int*)d_in[2];
    const float* eps   = (const float*)d_in[3];
    const float* W1    = (const float*)d_in[4];
    const float* b1    = (const float*)d_in[5];
    const float* W2    = (const float*)d_in[6];
    const float* b2    = (const float*)d_in[7];
    const float* gamma = (const float*)d_in[8];
    const float* beta  = (const float*)d_in[9];
    float* out = (float*)d_out;

    const int N = in_sizes[0] / D;
    const int E = in_sizes[1];
    const int n_elem4 = N * D / 4;
    const int NB = (N + 255) / 256;
    const int nvec = N * (D / 4);
    const int HB = (nvec + 255) / 256;

    float* buf1;
    uint4 *wf1, *wf2;
    cudaGetSymbolAddress((void**)&buf1, g_buf1_v4);
    cudaGetSymbolAddress((void**)&wf1, g_wf1);
    cudaGetSymbolAddress((void**)&wf2, g_wf2);

    // K1: zero counters/stats + W prep + h->fp16
    k_zero_wprep<<<NB + 2 + HB, 256>>>(h, W1, W2, N, NB, nvec);
    // K2: one-pass bucketed edge placement
    k_place<<<(E + 255) / 256, 256>>>(src, dst, E);
    // K3: fused gather + MLP -> buf1 (y2), fused BN stats
    k_fused<<<(N + TILE - 1) / TILE, 256>>>(h, eps, wf1, wf2, b1, b2, buf1, N);
    // K4: epilogue with merged BN finalize
    k_epilogue<<<2048, 256>>>(h, gamma, beta, out, 1.0f / (float)N, n_elem4);
}

// round 16
// speedup vs baseline: 1.1061x; 1.1061x over previous
#include <cuda_runtime.h>
#include <cuda_bf16.h>
#include <cuda_fp16.h>
#include <cstdint>
#include <math.h>

// GIN layer: out = h + relu(BN(relu(((1+eps)h + segsum(h[src]->dst)) @ W1 + b1) @ W2 + b2))
// Bucket CSR + fused gather->GEMM1->GEMM2 (split-bf16 mma.sync), R14 build (best: 217.2us)
// + probe launch so ncu's capture slot (4th launch) lands on k_fused
// + vectorized k_place.
#define D 128
#define MAXN 100000
#define CAP 96

// ---- scratch (__device__ globals; alloc-free rule) ----
__device__ float4 g_buf1_v4[MAXN * (D / 4)];   // y2
__device__ uint2 g_hhalf[MAXN * (D / 4)];      // h in fp16 (32 uint2 per row)
__device__ int g_cnt[MAXN];                    // per-node degree counters
__device__ int g_bucket[MAXN * CAP];           // src lists grouped by dst
__device__ uint4 g_wf1[4096], g_wf2[4096];     // W fragments (mma B layout, hi/lo interleaved)
__device__ float g_sum[D], g_sumsq[D];

// ---------------------------------------------------------------------------
__device__ __forceinline__ void split2(float2 v, uint32_t& hi, uint32_t& lo) {
    __nv_bfloat162 h = __floats2bfloat162_rn(v.x, v.y);
    float2 hf = __bfloat1622float2(h);
    __nv_bfloat162 l = __floats2bfloat162_rn(v.x - hf.x, v.y - hf.y);
    hi = *(uint32_t*)&h;
    lo = *(uint32_t*)&l;
}

__device__ __forceinline__ void mma16816(float* c, const uint32_t* a,
                                         uint32_t b0, uint32_t b1) {
    asm volatile(
        "mma.sync.aligned.m16n8k16.row.col.f32.bf16.bf16.f32 "
        "{%0,%1,%2,%3}, {%4,%5,%6,%7}, {%8,%9}, {%0,%1,%2,%3};"
        : "+f"(c[0]), "+f"(c[1]), "+f"(c[2]), "+f"(c[3])
        : "r"(a[0]), "r"(a[1]), "r"(a[2]), "r"(a[3]), "r"(b0), "r"(b1));
}

__device__ __forceinline__ void acc_half4(float4& acc, uint2 q) {
    __half2 a01 = *(__half2*)&q.x;
    __half2 a23 = *(__half2*)&q.y;
    float2 f01 = __half22float2(a01);
    float2 f23 = __half22float2(a23);
    acc.x += f01.x; acc.y += f01.y; acc.z += f23.x; acc.w += f23.y;
}

// ---------------------------------------------------------------------------
// K1: zero counters + stats; 2 blocks do W fragment prep; HB blocks convert h->fp16.
// ---------------------------------------------------------------------------
__global__ __launch_bounds__(256) void k_zero_wprep(const float* __restrict__ h,
                                                    const float* __restrict__ W1,
                                                    const float* __restrict__ W2,
                                                    int N, int NB, int nvec) {
    int b = blockIdx.x;
    if (b < NB) {
        int i = b * 256 + threadIdx.x;
        if (i < N) g_cnt[i] = 0;
        if (b == 0 && threadIdx.x < D) {
            g_sum[threadIdx.x] = 0.f;
            g_sumsq[threadIdx.x] = 0.f;
        }
        return;
    }
    if (b < NB + 2) {
        const float* W = (b == NB) ? W1 : W2;
        uint4* wf = (b == NB) ? g_wf1 : g_wf2;
        for (int item = threadIdx.x; item < 4096; item += 256) {
            int ks = item >> 9;
            int nt = (item >> 5) & 15;
            int lane = item & 31;
            int n = nt * 8 + (lane >> 2);
            int k0 = ks * 16 + (lane & 3) * 2;
            float2 p0 = make_float2(W[k0 * D + n], W[(k0 + 1) * D + n]);
            float2 p1 = make_float2(W[(k0 + 8) * D + n], W[(k0 + 9) * D + n]);
            uint4 q;
            split2(p0, q.x, q.z);
            split2(p1, q.y, q.w);
            wf[item] = q;
        }
        return;
    }
    int idx = (b - NB - 2) * 256 + threadIdx.x;
    if (idx < nvec) {
        float4 v = ((const float4*)h)[idx];
        __half2 h01 = __floats2half2_rn(v.x, v.y);
        __half2 h23 = __floats2half2_rn(v.z, v.w);
        g_hhalf[idx] = make_uint2(*(uint32_t*)&h01, *(uint32_t*)&h23);
    }
}

// ---------------------------------------------------------------------------
// K2: one-pass bucketed edge placement (4 edges per thread, int4 reads).
// ---------------------------------------------------------------------------
__global__ __launch_bounds__(256) void k_place(const int* __restrict__ src,
                                               const int* __restrict__ dst, int E) {
    int base = (blockIdx.x * 256 + threadIdx.x) * 4;
    if (base + 4 <= E) {
        int4 s4 = *(const int4*)(src + base);
        int4 d4 = *(const int4*)(dst + base);
        int p;
        p = atomicAdd(&g_cnt[d4.x], 1);
        if (p < CAP) g_bucket[(size_t)d4.x * CAP + p] = s4.x;
        p = atomicAdd(&g_cnt[d4.y], 1);
        if (p < CAP) g_bucket[(size_t)d4.y * CAP + p] = s4.y;
        p = atomicAdd(&g_cnt[d4.z], 1);
        if (p < CAP) g_bucket[(size_t)d4.z * CAP + p] = s4.z;
        p = atomicAdd(&g_cnt[d4.w], 1);
        if (p < CAP) g_bucket[(size_t)d4.w * CAP + p] = s4.w;
    } else {
        for (int e = base; e < E; e++) {
            int d = dst[e];
            int p = atomicAdd(&g_cnt[d], 1);
            if (p < CAP) g_bucket[(size_t)d * CAP + p] = src[e];
        }
    }
}

// ---------------------------------------------------------------------------
// Probe: no-op launch so the ncu capture slot (4th launch) lands on k_fused.
// ---------------------------------------------------------------------------
__global__ void k_probe() {}

// ---------------------------------------------------------------------------
// Fused: gather-aggregate + MLP. CTA = 64 nodes, 8 warps, warp w -> nodes w*8..+7.
// Phase A: gather (fp16 neighbor rows, fp32 self) -> split bf16 hi/lo smem planes.
// Phase B: stage-1 GEMM, relu(+b1) overwrites planes.
// Phase C: stage-2 GEMM -> y2 gmem + fused BN column stats.
// Pitch 136 elems (68 words/row, mod 32 = 4) -> conflict-free fragment LDS.
// ---------------------------------------------------------------------------
#define PITCH 136
#define TILE 64
__global__ __launch_bounds__(256) void k_fused(
    const float* __restrict__ h, const float* __restrict__ eps,
    const uint4* __restrict__ W1f, const uint4* __restrict__ W2f,
    const float* __restrict__ b1, const float* __restrict__ b2,
    float* __restrict__ Y, int N) {
    __shared__ __nv_bfloat16 plhi[TILE * PITCH];
    __shared__ __nv_bfloat16 pllo[TILE * PITCH];
    __shared__ float csum[D], csumsq[D];

    const int t = threadIdx.x;
    const int w = t >> 5;
    const int lane = t & 31;

    if (t < D) { csum[t] = 0.f; csumsq[t] = 0.f; }

    // ---------------- Phase A: gather ----------------
    {
        const float4* h4 = (const float4*)h;
        const float s = 1.0f + eps[0];
        #pragma unroll 1
        for (int i = 0; i < 8; i++) {
            int nl = w * 8 + i;
            int n = blockIdx.x * TILE + nl;
            float4 acc = make_float4(0.f, 0.f, 0.f, 0.f);
            if (n < N) {
                acc = __ldg(&h4[(size_t)n * 32 + lane]);
                acc.x *= s; acc.y *= s; acc.z *= s; acc.w *= s;
                int deg = min(g_cnt[n], CAP);
                const int* bucket = g_bucket + (size_t)n * CAP;
                int j = 0;
                for (; j + 8 <= deg; j += 8) {
                    int si[8];
                    #pragma unroll
                    for (int u = 0; u < 8; u++) si[u] = bucket[j + u];
                    uint2 a[8];
                    #pragma unroll
                    for (int u = 0; u < 8; u++)
                        a[u] = __ldg(&g_hhalf[(size_t)si[u] * 32 + lane]);
                    #pragma unroll
                    for (int u = 0; u < 8; u++) acc_half4(acc, a[u]);
                }
                for (; j + 4 <= deg; j += 4) {
                    int si[4];
                    #pragma unroll
                    for (int u = 0; u < 4; u++) si[u] = bucket[j + u];
                    uint2 a[4];
                    #pragma unroll
                    for (int u = 0; u < 4; u++)
                        a[u] = __ldg(&g_hhalf[(size_t)si[u] * 32 + lane]);
                    #pragma unroll
                    for (int u = 0; u < 4; u++) acc_half4(acc, a[u]);
                }
                for (; j < deg; j++) {
                    uint2 a0 = __ldg(&g_hhalf[(size_t)bucket[j] * 32 + lane]);
                    acc_half4(acc, a0);
                }
            }
            uint32_t hi01, lo01, hi23, lo23;
            split2(make_float2(acc.x, acc.y), hi01, lo01);
            split2(make_float2(acc.z, acc.w), hi23, lo23);
            *(uint2*)&plhi[nl * PITCH + lane * 4] = make_uint2(hi01, hi23);
            *(uint2*)&pllo[nl * PITCH + lane * 4] = make_uint2(lo01, lo23);
        }
    }
    __syncthreads();

    const int rloc = (w >> 1) * 16 + (lane >> 2);
    const int r0 = blockIdx.x * TILE + rloc;
    const int kq = (lane & 3) * 2;
    const int nhalf = w & 1;
    const bool rv0 = r0 < N;
    const bool rv1 = (r0 + 8) < N;

    float acc[8][4];

    // ---------------- Phase B: stage-1 GEMM ----------------
    #pragma unroll
    for (int nt = 0; nt < 8; nt++)
        #pragma unroll
        for (int j = 0; j < 4; j++) acc[nt][j] = 0.f;

    #pragma unroll
    for (int ks = 0; ks < 8; ks++) {
        const int k0 = ks * 16 + kq;
        uint32_t ah[4], al[4];
        ah[0] = *(const uint32_t*)&plhi[rloc * PITCH + k0];
        ah[1] = *(const uint32_t*)&plhi[(rloc + 8) * PITCH + k0];
        ah[2] = *(const uint32_t*)&plhi[rloc * PITCH + k0 + 8];
        ah[3] = *(const uint32_t*)&plhi[(rloc + 8) * PITCH + k0 + 8];
        al[0] = *(const uint32_t*)&pllo[rloc * PITCH + k0];
        al[1] = *(const uint32_t*)&pllo[(rloc + 8) * PITCH + k0];
        al[2] = *(const uint32_t*)&pllo[rloc * PITCH + k0 + 8];
        al[3] = *(const uint32_t*)&pllo[(rloc + 8) * PITCH + k0 + 8];
        #pragma unroll
        for (int nt = 0; nt < 8; nt++) {
            uint4 q = __ldg(&W1f[(ks * 16 + nhalf * 8 + nt) * 32 + lane]);
            mma16816(acc[nt], ah, q.x, q.y);
            mma16816(acc[nt], al, q.x, q.y);
            mma16816(acc[nt], ah, q.z, q.w);
        }
    }
    __syncthreads();   // all reads of x planes done before overwrite

    // stage-1 epilogue: relu(acc+b1) -> planes (reuse)
    #pragma unroll
    for (int nt = 0; nt < 8; nt++) {
        const int n0 = nhalf * 64 + nt * 8 + kq;
        float2 bv = __ldg((const float2*)(b1 + n0));
        float2 p0 = make_float2(fmaxf(acc[nt][0] + bv.x, 0.f),
                                fmaxf(acc[nt][1] + bv.y, 0.f));
        float2 p1 = make_float2(fmaxf(acc[nt][2] + bv.x, 0.f),
                                fmaxf(acc[nt][3] + bv.y, 0.f));
        uint32_t hi0, lo0, hi1, lo1;
        split2(p0, hi0, lo0);
        split2(p1, hi1, lo1);
        *(uint32_t*)&plhi[rloc * PITCH + n0] = hi0;
        *(uint32_t*)&pllo[rloc * PITCH + n0] = lo0;
        *(uint32_t*)&plhi[(rloc + 8) * PITCH + n0] = hi1;
        *(uint32_t*)&pllo[(rloc + 8) * PITCH + n0] = lo1;
    }
    __syncthreads();

    // ---------------- Phase C: stage-2 GEMM ----------------
    #pragma unroll
    for (int nt = 0; nt < 8; nt++)
        #pragma unroll
        for (int j = 0; j < 4; j++) acc[nt][j] = 0.f;

    #pragma unroll
    for (int ks = 0; ks < 8; ks++) {
        const int k0 = ks * 16 + kq;
        uint32_t ah[4], al[4];
        ah[0] = *(const uint32_t*)&plhi[rloc * PITCH + k0];
        ah[1] = *(const uint32_t*)&plhi[(rloc + 8) * PITCH + k0];
        ah[2] = *(const uint32_t*)&plhi[rloc * PITCH + k0 + 8];
        ah[3] = *(const uint32_t*)&plhi[(rloc + 8) * PITCH + k0 + 8];
        al[0] = *(const uint32_t*)&pllo[rloc * PITCH + k0];
        al[1] = *(const uint32_t*)&pllo[(rloc + 8) * PITCH + k0];
        al[2] = *(const uint32_t*)&pllo[rloc * PITCH + k0 + 8];
        al[3] = *(const uint32_t*)&pllo[(rloc + 8) * PITCH + k0 + 8];
        #pragma unroll
        for (int nt = 0; nt < 8; nt++) {
            uint4 q = __ldg(&W2f[(ks * 16 + nhalf * 8 + nt) * 32 + lane]);
            mma16816(acc[nt], ah, q.x, q.y);
            mma16816(acc[nt], al, q.x, q.y);
            mma16816(acc[nt], ah, q.z, q.w);
        }
    }

    // stage-2 epilogue: + b2, write y2, fused BN stats
    #pragma unroll
    for (int nt = 0; nt < 8; nt++) {
        const int n0 = nhalf * 64 + nt * 8 + kq;
        float2 bv = __ldg((const float2*)(b2 + n0));
        float ox0 = acc[nt][0] + bv.x;
        float oy0 = acc[nt][1] + bv.y;
        float ox1 = acc[nt][2] + bv.x;
        float oy1 = acc[nt][3] + bv.y;
        float sA = 0.f, sB = 0.f, qA = 0.f, qB = 0.f;
        if (rv0) {
            *(float2*)(Y + (size_t)r0 * D + n0) = make_float2(ox0, oy0);
            sA += ox0; qA = fmaf(ox0, ox0, qA);
            sB += oy0; qB = fmaf(oy0, oy0, qB);
        }
        if (rv1) {
            *(float2*)(Y + (size_t)(r0 + 8) * D + n0) = make_float2(ox1, oy1);
            sA += ox1; qA = fmaf(ox1, ox1, qA);
            sB += oy1; qB = fmaf(oy1, oy1, qB);
        }
        #pragma unroll
        for (int off = 4; off <= 16; off <<= 1) {
            sA += __shfl_xor_sync(0xFFFFFFFF, sA, off);
            sB += __shfl_xor_sync(0xFFFFFFFF, sB, off);
            qA += __shfl_xor_sync(0xFFFFFFFF, qA, off);
            qB += __shfl_xor_sync(0xFFFFFFFF, qB, off);
        }
        if (lane < 4) {
            atomicAdd(&csum[n0], sA);
            atomicAdd(&csum[n0 + 1], sB);
            atomicAdd(&csumsq[n0], qA);
            atomicAdd(&csumsq[n0 + 1], qB);
        }
    }

    __syncthreads();
    if (t < D) {
        atomicAdd(&g_sum[t], csum[t]);
        atomicAdd(&g_sumsq[t], csumsq[t]);
    }
}

// ---------------------------------------------------------------------------
// Epilogue (merged BN finalize): out = h + relu(y2 * scale + shift)
// ---------------------------------------------------------------------------
__global__ __launch_bounds__(256) void k_epilogue(const float* __restrict__ h,
                                                  const float* __restrict__ gamma,
                                                  const float* __restrict__ beta,
                                                  float* __restrict__ out,
                                                  float invN, int n_elem4) {
    __shared__ float s_scale[D], s_shift[D];
    if (threadIdx.x < D) {
        int c = threadIdx.x;
        float mean = g_sum[c] * invN;
        float var = g_sumsq[c] * invN - mean * mean;
        float rstd = rsqrtf(var + 1e-5f);
        float sc = rstd * gamma[c];
        s_scale[c] = sc;
        s_shift[c] = beta[c] - mean * sc;
    }
    __syncthreads();
    int i = blockIdx.x * blockDim.x + threadIdx.x;
    int stride = gridDim.x * blockDim.x;
    const float4* h4 = (const float4*)h;
    float4* o4 = (float4*)out;
    for (; i < n_elem4; i += stride) {
        int c4 = (i & 31);
        float4 sc = ((const float4*)s_scale)[c4];
        float4 sh = ((const float4*)s_shift)[c4];
        float4 y = g_buf1_v4[i];
        float4 hv = h4[i];
        float4 o;
        o.x = hv.x + fmaxf(fmaf(y.x, sc.x, sh.x), 0.f);
        o.y = hv.y + fmaxf(fmaf(y.y, sc.y, sh.y), 0.f);
        o.z = hv.z + fmaxf(fmaf(y.z, sc.z, sh.z), 0.f);
        o.w = hv.w + fmaxf(fmaf(y.w, sc.w, sh.w), 0.f);
        o4[i] = o;
    }
}

// ---------------------------------------------------------------------------
// Inputs: h, src, dst, eps, W1, b1, W2, b2, gamma, beta
// ---------------------------------------------------------------------------
extern "C" void kernel_launch(void* const* d_in, const int* in_sizes, int n_in,
                              void* d_out, int out_size) {
    const float* h     = (const float*)d_in[0];
    const int*   src   = (const int*)d_in[1];
    const int*   dst   = (const int*)d_in[2];
    const float* eps   = (const float*)d_in[3];
    const float* W1    = (const float*)d_in[4];
    const float* b1    = (const float*)d_in[5];
    const float* W2    = (const float*)d_in[6];
    const float* b2    = (const float*)d_in[7];
    const float* gamma = (const float*)d_in[8];
    const float* beta  = (const float*)d_in[9];
    float* out = (float*)d_out;

    const int N = in_sizes[0] / D;
    const int E = in_sizes[1];
    const int n_elem4 = N * D / 4;
    const int NB = (N + 255) / 256;
    const int nvec = N * (D / 4);
    const int HB = (nvec + 255) / 256;

    float* buf1;
    uint4 *wf1, *wf2;
    cudaGetSymbolAddress((void**)&buf1, g_buf1_v4);
    cudaGetSymbolAddress((void**)&wf1, g_wf1);
    cudaGetSymbolAddress((void**)&wf2, g_wf2);

    // K1: zero counters/stats + W prep + h->fp16
    k_zero_wprep<<<NB + 2 + HB, 256>>>(h, W1, W2, N, NB, nvec);
    // K2: one-pass bucketed edge placement (vectorized)
    k_place<<<(E / 4 + 255) / 256 + 1, 256>>>(src, dst, E);
    // K3: probe (aligns ncu capture slot onto k_fused)
    k_probe<<<1, 32>>>();
    // K4: fused gather + MLP -> buf1 (y2), fused BN stats
    k_fused<<<(N + TILE - 1) / TILE, 256>>>(h, eps, wf1, wf2, b1, b2, buf1, N);
    // K5: epilogue with merged BN finalize
    k_epilogue<<<2048, 256>>>(h, gamma, beta, out, 1.0f / (float)N, n_elem4);
}

// round 17
// speedup vs baseline: 1.1882x; 1.0742x over previous
#include <cuda_runtime.h>
#include <cuda_bf16.h>
#include <cuda_fp16.h>
#include <cstdint>
#include <math.h>

// GIN layer: out = h + relu(BN(relu(((1+eps)h + segsum(h[src]->dst)) @ W1 + b1) @ W2 + b2))
// Bucket CSR + fused gather->GEMM1->GEMM2 (split-bf16 mma.sync).
// R16 finding: k_fused is latency-bound at occ=36% (regs=78 -> 3 CTAs/SM).
// Fix: __launch_bounds__(256, 4) to force regs<=64 -> 4 CTAs/SM.
#define D 128
#define MAXN 100000
#define CAP 96

// ---- scratch (__device__ globals; alloc-free rule) ----
__device__ float4 g_buf1_v4[MAXN * (D / 4)];   // y2
__device__ uint2 g_hhalf[MAXN * (D / 4)];      // h in fp16 (32 uint2 per row)
__device__ int g_cnt[MAXN];                    // per-node degree counters
__device__ int g_bucket[MAXN * CAP];           // src lists grouped by dst
__device__ uint4 g_wf1[4096], g_wf2[4096];     // W fragments (mma B layout, hi/lo interleaved)
__device__ float g_sum[D], g_sumsq[D];

// ---------------------------------------------------------------------------
__device__ __forceinline__ void split2(float2 v, uint32_t& hi, uint32_t& lo) {
    __nv_bfloat162 h = __floats2bfloat162_rn(v.x, v.y);
    float2 hf = __bfloat1622float2(h);
    __nv_bfloat162 l = __floats2bfloat162_rn(v.x - hf.x, v.y - hf.y);
    hi = *(uint32_t*)&h;
    lo = *(uint32_t*)&l;
}

__device__ __forceinline__ void mma16816(float* c, const uint32_t* a,
                                         uint32_t b0, uint32_t b1) {
    asm volatile(
        "mma.sync.aligned.m16n8k16.row.col.f32.bf16.bf16.f32 "
        "{%0,%1,%2,%3}, {%4,%5,%6,%7}, {%8,%9}, {%0,%1,%2,%3};"
        : "+f"(c[0]), "+f"(c[1]), "+f"(c[2]), "+f"(c[3])
        : "r"(a[0]), "r"(a[1]), "r"(a[2]), "r"(a[3]), "r"(b0), "r"(b1));
}

__device__ __forceinline__ void acc_half4(float4& acc, uint2 q) {
    __half2 a01 = *(__half2*)&q.x;
    __half2 a23 = *(__half2*)&q.y;
    float2 f01 = __half22float2(a01);
    float2 f23 = __half22float2(a23);
    acc.x += f01.x; acc.y += f01.y; acc.z += f23.x; acc.w += f23.y;
}

// ---------------------------------------------------------------------------
// K1: zero counters + stats; 2 blocks do W fragment prep; HB blocks convert h->fp16.
// ---------------------------------------------------------------------------
__global__ __launch_bounds__(256) void k_zero_wprep(const float* __restrict__ h,
                                                    const float* __restrict__ W1,
                                                    const float* __restrict__ W2,
                                                    int N, int NB, int nvec) {
    int b = blockIdx.x;
    if (b < NB) {
        int i = b * 256 + threadIdx.x;
        if (i < N) g_cnt[i] = 0;
        if (b == 0 && threadIdx.x < D) {
            g_sum[threadIdx.x] = 0.f;
            g_sumsq[threadIdx.x] = 0.f;
        }
        return;
    }
    if (b < NB + 2) {
        const float* W = (b == NB) ? W1 : W2;
        uint4* wf = (b == NB) ? g_wf1 : g_wf2;
        for (int item = threadIdx.x; item < 4096; item += 256) {
            int ks = item >> 9;
            int nt = (item >> 5) & 15;
            int lane = item & 31;
            int n = nt * 8 + (lane >> 2);
            int k0 = ks * 16 + (lane & 3) * 2;
            float2 p0 = make_float2(W[k0 * D + n], W[(k0 + 1) * D + n]);
            float2 p1 = make_float2(W[(k0 + 8) * D + n], W[(k0 + 9) * D + n]);
            uint4 q;
            split2(p0, q.x, q.z);
            split2(p1, q.y, q.w);
            wf[item] = q;
        }
        return;
    }
    int idx = (b - NB - 2) * 256 + threadIdx.x;
    if (idx < nvec) {
        float4 v = ((const float4*)h)[idx];
        __half2 h01 = __floats2half2_rn(v.x, v.y);
        __half2 h23 = __floats2half2_rn(v.z, v.w);
        g_hhalf[idx] = make_uint2(*(uint32_t*)&h01, *(uint32_t*)&h23);
    }
}

// ---------------------------------------------------------------------------
// K2: one-pass bucketed edge placement (scalar — best measured variant).
// ---------------------------------------------------------------------------
__global__ __launch_bounds__(256) void k_place(const int* __restrict__ src,
                                               const int* __restrict__ dst, int E) {
    int e = blockIdx.x * 256 + threadIdx.x;
    if (e >= E) return;
    int d = dst[e];
    int pos = atomicAdd(&g_cnt[d], 1);
    if (pos < CAP) g_bucket[(size_t)d * CAP + pos] = src[e];
}

// ---------------------------------------------------------------------------
// Probe: no-op launch so the ncu capture slot (4th launch) lands on k_fused.
// ---------------------------------------------------------------------------
__global__ void k_probe() {}

// ---------------------------------------------------------------------------
// Fused: gather-aggregate + MLP. CTA = 64 nodes, 8 warps, warp w -> nodes w*8..+7.
// Phase A: gather (fp16 neighbor rows, fp32 self) -> split bf16 hi/lo smem planes.
// Phase B: stage-1 GEMM, relu(+b1) overwrites planes.
// Phase C: stage-2 GEMM -> y2 gmem + fused BN column stats.
// Pitch 136 elems (68 words/row, mod 32 = 4) -> conflict-free fragment LDS.
// __launch_bounds__(256, 4): cap regs at 64 -> 4 CTAs/SM (occ 36% -> 50%).
// ---------------------------------------------------------------------------
#define PITCH 136
#define TILE 64
__global__ __launch_bounds__(256, 4) void k_fused(
    const float* __restrict__ h, const float* __restrict__ eps,
    const uint4* __restrict__ W1f, const uint4* __restrict__ W2f,
    const float* __restrict__ b1, const float* __restrict__ b2,
    float* __restrict__ Y, int N) {
    __shared__ __nv_bfloat16 plhi[TILE * PITCH];
    __shared__ __nv_bfloat16 pllo[TILE * PITCH];
    __shared__ float csum[D], csumsq[D];

    const int t = threadIdx.x;
    const int w = t >> 5;
    const int lane = t & 31;

    if (t < D) { csum[t] = 0.f; csumsq[t] = 0.f; }

    // ---------------- Phase A: gather ----------------
    {
        const float4* h4 = (const float4*)h;
        const float s = 1.0f + eps[0];
        #pragma unroll 1
        for (int i = 0; i < 8; i++) {
            int nl = w * 8 + i;
            int n = blockIdx.x * TILE + nl;
            float4 acc = make_float4(0.f, 0.f, 0.f, 0.f);
            if (n < N) {
                acc = __ldg(&h4[(size_t)n * 32 + lane]);
                acc.x *= s; acc.y *= s; acc.z *= s; acc.w *= s;
                int deg = min(g_cnt[n], CAP);
                const int* bucket = g_bucket + (size_t)n * CAP;
                int j = 0;
                for (; j + 8 <= deg; j += 8) {
                    int si[8];
                    #pragma unroll
                    for (int u = 0; u < 8; u++) si[u] = bucket[j + u];
                    uint2 a[8];
                    #pragma unroll
                    for (int u = 0; u < 8; u++)
                        a[u] = __ldg(&g_hhalf[(size_t)si[u] * 32 + lane]);
                    #pragma unroll
                    for (int u = 0; u < 8; u++) acc_half4(acc, a[u]);
                }
                for (; j + 4 <= deg; j += 4) {
                    int si[4];
                    #pragma unroll
                    for (int u = 0; u < 4; u++) si[u] = bucket[j + u];
                    uint2 a[4];
                    #pragma unroll
                    for (int u = 0; u < 4; u++)
                        a[u] = __ldg(&g_hhalf[(size_t)si[u] * 32 + lane]);
                    #pragma unroll
                    for (int u = 0; u < 4; u++) acc_half4(acc, a[u]);
                }
                for (; j < deg; j++) {
                    uint2 a0 = __ldg(&g_hhalf[(size_t)bucket[j] * 32 + lane]);
                    acc_half4(acc, a0);
                }
            }
            uint32_t hi01, lo01, hi23, lo23;
            split2(make_float2(acc.x, acc.y), hi01, lo01);
            split2(make_float2(acc.z, acc.w), hi23, lo23);
            *(uint2*)&plhi[nl * PITCH + lane * 4] = make_uint2(hi01, hi23);
            *(uint2*)&pllo[nl * PITCH + lane * 4] = make_uint2(lo01, lo23);
        }
    }
    __syncthreads();

    const int rloc = (w >> 1) * 16 + (lane >> 2);
    const int r0 = blockIdx.x * TILE + rloc;
    const int kq = (lane & 3) * 2;
    const int nhalf = w & 1;
    const bool rv0 = r0 < N;
    const bool rv1 = (r0 + 8) < N;

    float acc[8][4];

    // ---------------- Phase B: stage-1 GEMM ----------------
    #pragma unroll
    for (int nt = 0; nt < 8; nt++)
        #pragma unroll
        for (int j = 0; j < 4; j++) acc[nt][j] = 0.f;

    #pragma unroll
    for (int ks = 0; ks < 8; ks++) {
        const int k0 = ks * 16 + kq;
        uint32_t ah[4], al[4];
        ah[0] = *(const uint32_t*)&plhi[rloc * PITCH + k0];
        ah[1] = *(const uint32_t*)&plhi[(rloc + 8) * PITCH + k0];
        ah[2] = *(const uint32_t*)&plhi[rloc * PITCH + k0 + 8];
        ah[3] = *(const uint32_t*)&plhi[(rloc + 8) * PITCH + k0 + 8];
        al[0] = *(const uint32_t*)&pllo[rloc * PITCH + k0];
        al[1] = *(const uint32_t*)&pllo[(rloc + 8) * PITCH + k0];
        al[2] = *(const uint32_t*)&pllo[rloc * PITCH + k0 + 8];
        al[3] = *(const uint32_t*)&pllo[(rloc + 8) * PITCH + k0 + 8];
        #pragma unroll
        for (int nt = 0; nt < 8; nt++) {
            uint4 q = __ldg(&W1f[(ks * 16 + nhalf * 8 + nt) * 32 + lane]);
            mma16816(acc[nt], ah, q.x, q.y);
            mma16816(acc[nt], al, q.x, q.y);
            mma16816(acc[nt], ah, q.z, q.w);
        }
    }
    __syncthreads();   // all reads of x planes done before overwrite

    // stage-1 epilogue: relu(acc+b1) -> planes (reuse)
    #pragma unroll
    for (int nt = 0; nt < 8; nt++) {
        const int n0 = nhalf * 64 + nt * 8 + kq;
        float2 bv = __ldg((const float2*)(b1 + n0));
        float2 p0 = make_float2(fmaxf(acc[nt][0] + bv.x, 0.f),
                                fmaxf(acc[nt][1] + bv.y, 0.f));
        float2 p1 = make_float2(fmaxf(acc[nt][2] + bv.x, 0.f),
                                fmaxf(acc[nt][3] + bv.y, 0.f));
        uint32_t hi0, lo0, hi1, lo1;
        split2(p0, hi0, lo0);
        split2(p1, hi1, lo1);
        *(uint32_t*)&plhi[rloc * PITCH + n0] = hi0;
        *(uint32_t*)&pllo[rloc * PITCH + n0] = lo0;
        *(uint32_t*)&plhi[(rloc + 8) * PITCH + n0] = hi1;
        *(uint32_t*)&pllo[(rloc + 8) * PITCH + n0] = lo1;
    }
    __syncthreads();

    // ---------------- Phase C: stage-2 GEMM ----------------
    #pragma unroll
    for (int nt = 0; nt < 8; nt++)
        #pragma unroll
        for (int j = 0; j < 4; j++) acc[nt][j] = 0.f;

    #pragma unroll
    for (int ks = 0; ks < 8; ks++) {
        const int k0 = ks * 16 + kq;
        uint32_t ah[4], al[4];
        ah[0] = *(const uint32_t*)&plhi[rloc * PITCH + k0];
        ah[1] = *(const uint32_t*)&plhi[(rloc + 8) * PITCH + k0];
        ah[2] = *(const uint32_t*)&plhi[rloc * PITCH + k0 + 8];
        ah[3] = *(const uint32_t*)&plhi[(rloc + 8) * PITCH + k0 + 8];
        al[0] = *(const uint32_t*)&pllo[rloc * PITCH + k0];
        al[1] = *(const uint32_t*)&pllo[(rloc + 8) * PITCH + k0];
        al[2] = *(const uint32_t*)&pllo[rloc * PITCH + k0 + 8];
        al[3] = *(const uint32_t*)&pllo[(rloc + 8) * PITCH + k0 + 8];
        #pragma unroll
        for (int nt = 0; nt < 8; nt++) {
            uint4 q = __ldg(&W2f[(ks * 16 + nhalf * 8 + nt) * 32 + lane]);
            mma16816(acc[nt], ah, q.x, q.y);
            mma16816(acc[nt], al, q.x, q.y);
            mma16816(acc[nt], ah, q.z, q.w);
        }
    }

    // stage-2 epilogue: + b2, write y2, fused BN stats
    #pragma unroll
    for (int nt = 0; nt < 8; nt++) {
        const int n0 = nhalf * 64 + nt * 8 + kq;
        float2 bv = __ldg((const float2*)(b2 + n0));
        float ox0 = acc[nt][0] + bv.x;
        float oy0 = acc[nt][1] + bv.y;
        float ox1 = acc[nt][2] + bv.x;
        float oy1 = acc[nt][3] + bv.y;
        float sA = 0.f, sB = 0.f, qA = 0.f, qB = 0.f;
        if (rv0) {
            *(float2*)(Y + (size_t)r0 * D + n0) = make_float2(ox0, oy0);
            sA += ox0; qA = fmaf(ox0, ox0, qA);
            sB += oy0; qB = fmaf(oy0, oy0, qB);
        }
        if (rv1) {
            *(float2*)(Y + (size_t)(r0 + 8) * D + n0) = make_float2(ox1, oy1);
            sA += ox1; qA = fmaf(ox1, ox1, qA);
            sB += oy1; qB = fmaf(oy1, oy1, qB);
        }
        #pragma unroll
        for (int off = 4; off <= 16; off <<= 1) {
            sA += __shfl_xor_sync(0xFFFFFFFF, sA, off);
            sB += __shfl_xor_sync(0xFFFFFFFF, sB, off);
            qA += __shfl_xor_sync(0xFFFFFFFF, qA, off);
            qB += __shfl_xor_sync(0xFFFFFFFF, qB, off);
        }
        if (lane < 4) {
            atomicAdd(&csum[n0], sA);
            atomicAdd(&csum[n0 + 1], sB);
            atomicAdd(&csumsq[n0], qA);
            atomicAdd(&csumsq[n0 + 1], qB);
        }
    }

    __syncthreads();
    if (t < D) {
        atomicAdd(&g_sum[t], csum[t]);
        atomicAdd(&g_sumsq[t], csumsq[t]);
    }
}

// ---------------------------------------------------------------------------
// Epilogue (merged BN finalize): out = h + relu(y2 * scale + shift)
// ---------------------------------------------------------------------------
__global__ __launch_bounds__(256) void k_epilogue(const float* __restrict__ h,
                                                  const float* __restrict__ gamma,
                                                  const float* __restrict__ beta,
                                                  float* __restrict__ out,
                                                  float invN, int n_elem4) {
    __shared__ float s_scale[D], s_shift[D];
    if (threadIdx.x < D) {
        int c = threadIdx.x;
        float mean = g_sum[c] * invN;
        float var = g_sumsq[c] * invN - mean * mean;
        float rstd = rsqrtf(var + 1e-5f);
        float sc = rstd * gamma[c];
        s_scale[c] = sc;
        s_shift[c] = beta[c] - mean * sc;
    }
    __syncthreads();
    int i = blockIdx.x * blockDim.x + threadIdx.x;
    int stride = gridDim.x * blockDim.x;
    const float4* h4 = (const float4*)h;
    float4* o4 = (float4*)out;
    for (; i < n_elem4; i += stride) {
        int c4 = (i & 31);
        float4 sc = ((const float4*)s_scale)[c4];
        float4 sh = ((const float4*)s_shift)[c4];
        float4 y = g_buf1_v4[i];
        float4 hv = h4[i];
        float4 o;
        o.x = hv.x + fmaxf(fmaf(y.x, sc.x, sh.x), 0.f);
        o.y = hv.y + fmaxf(fmaf(y.y, sc.y, sh.y), 0.f);
        o.z = hv.z + fmaxf(fmaf(y.z, sc.z, sh.z), 0.f);
        o.w = hv.w + fmaxf(fmaf(y.w, sc.w, sh.w), 0.f);
        o4[i] = o;
    }
}

// ---------------------------------------------------------------------------
// Inputs: h, src, dst, eps, W1, b1, W2, b2, gamma, beta
// ---------------------------------------------------------------------------
extern "C" void kernel_launch(void* const* d_in, const int* in_sizes, int n_in,
                              void* d_out, int out_size) {
    const float* h     = (const float*)d_in[0];
    const int*   src   = (const int*)d_in[1];
    const int*   dst   = (const int*)d_in[2];
    const float* eps   = (const float*)d_in[3];
    const float* W1    = (const float*)d_in[4];
    const float* b1    = (const float*)d_in[5];
    const float* W2    = (const float*)d_in[6];
    const float* b2    = (const float*)d_in[7];
    const float* gamma = (const float*)d_in[8];
    const float* beta  = (const float*)d_in[9];
    float* out = (float*)d_out;

    const int N = in_sizes[0] / D;
    const int E = in_sizes[1];
    const int n_elem4 = N * D / 4;
    const int NB = (N + 255) / 256;
    const int nvec = N * (D / 4);
    const int HB = (nvec + 255) / 256;

    float* buf1;
    uint4 *wf1, *wf2;
    cudaGetSymbolAddress((void**)&buf1, g_buf1_v4);
    cudaGetSymbolAddress((void**)&wf1, g_wf1);
    cudaGetSymbolAddress((void**)&wf2, g_wf2);

    // K1: zero counters/stats + W prep + h->fp16
    k_zero_wprep<<<NB + 2 + HB, 256>>>(h, W1, W2, N, NB, nvec);
    // K2: one-pass bucketed edge placement
    k_place<<<(E + 255) / 256, 256>>>(src, dst, E);
    // K3: probe (aligns ncu capture slot onto k_fused)
    k_probe<<<1, 32>>>();
    // K4: fused gather + MLP -> buf1 (y2), fused BN stats
    k_fused<<<(N + TILE - 1) / TILE, 256>>>(h, eps, wf1, wf2, b1, b2, buf1, N);
    // K5: epilogue with merged BN finalize
    k_epilogue<<<2048, 256>>>(h, gamma, beta, out, 1.0f / (float)N, n_elem4);
}